// round 1
// baseline (speedup 1.0000x reference)
#include <cuda_runtime.h>
#include <math.h>

#define BATCH 4
#define SEQ   2048
#define DIM   768

// ---------------- device scratch (allocation-free per harness rules) -------
__device__ float g_Q[BATCH * SEQ * DIM];            // 25.2 MB
__device__ float g_K[BATCH * SEQ * DIM];            // 25.2 MB
__device__ float g_V[BATCH * SEQ * DIM];            // 25.2 MB
__device__ float g_S[(size_t)BATCH * SEQ * SEQ];    // 67.1 MB (scores, softmax in-place)

// ---------------- 128x128x16 fp32 micro-GEMM core --------------------------
// 256 threads, each computes an 8x8 microtile. As/Bs hold K-major (transposed)
// tiles: sm[k][row].
__device__ __forceinline__ void mma_16(const float (*As)[128], const float (*Bs)[128],
                                       int ty, int tx, float acc[8][8]) {
#pragma unroll
    for (int k = 0; k < 16; ++k) {
        float a[8], b[8];
        *(float4*)&a[0] = *(const float4*)&As[k][ty * 8 + 0];
        *(float4*)&a[4] = *(const float4*)&As[k][ty * 8 + 4];
        *(float4*)&b[0] = *(const float4*)&Bs[k][tx * 8 + 0];
        *(float4*)&b[4] = *(const float4*)&Bs[k][tx * 8 + 4];
#pragma unroll
        for (int i = 0; i < 8; ++i)
#pragma unroll
            for (int j = 0; j < 8; ++j)
                acc[i][j] += a[i] * b[j];
    }
}

// Load a 128(rows) x 16(k) tile from row-major src (row stride ld), starting at
// (row0, kk), storing transposed into sm[k][row]. 256 threads.
__device__ __forceinline__ void load_tile_T(const float* __restrict__ src, int row0,
                                            int kk, int ld, float (*sm)[128], int tid) {
    int lr = tid >> 2;          // 0..63
    int lc = (tid & 3) << 2;    // 0,4,8,12
#pragma unroll
    for (int i = 0; i < 2; ++i) {
        int r = lr + i * 64;
        float4 v = *(const float4*)(src + (long)(row0 + r) * ld + kk + lc);
        sm[lc + 0][r] = v.x;
        sm[lc + 1][r] = v.y;
        sm[lc + 2][r] = v.z;
        sm[lc + 3][r] = v.w;
    }
}

// ---------------- kernel 1: fused QKV projection (NT GEMM) -----------------
// C[m][n] = sum_k x[m][k] * W[n][k];  M=B*S=8192, N=3*768 (Wq|Wk|Wv), K=768
__global__ __launch_bounds__(256) void qkv_kernel(const float* __restrict__ x,
                                                  const float* __restrict__ Wq,
                                                  const float* __restrict__ Wk,
                                                  const float* __restrict__ Wv) {
    __shared__ float As[16][128];
    __shared__ float Bs[16][128];
    const int tid = threadIdx.x;
    const int tx = tid & 15, ty = tid >> 4;
    const int m0 = blockIdx.x * 128;
    const int ng = blockIdx.y * 128;        // 0..2303, tile lies in one matrix (768%128==0)
    const int mat = ng / DIM;
    const int n0 = ng % DIM;
    const float* __restrict__ W = (mat == 0) ? Wq : ((mat == 1) ? Wk : Wv);

    float acc[8][8];
#pragma unroll
    for (int i = 0; i < 8; ++i)
#pragma unroll
        for (int j = 0; j < 8; ++j) acc[i][j] = 0.f;

    for (int kk = 0; kk < DIM; kk += 16) {
        load_tile_T(x, m0, kk, DIM, As, tid);
        load_tile_T(W, n0, kk, DIM, Bs, tid);
        __syncthreads();
        mma_16(As, Bs, ty, tx, acc);
        __syncthreads();
    }

    float* dst = (mat == 0) ? g_Q : ((mat == 1) ? g_K : g_V);
#pragma unroll
    for (int i = 0; i < 8; ++i) {
        float4 v0 = make_float4(acc[i][0], acc[i][1], acc[i][2], acc[i][3]);
        float4 v1 = make_float4(acc[i][4], acc[i][5], acc[i][6], acc[i][7]);
        long base = (long)(m0 + ty * 8 + i) * DIM + n0 + tx * 8;
        *(float4*)(dst + base)     = v0;
        *(float4*)(dst + base + 4) = v1;
    }
}

// ---------------- kernel 2: causal scores S = scale * Q K^T (NT GEMM) ------
// Per batch; skips tiles entirely above the diagonal (never read downstream).
__global__ __launch_bounds__(256) void scores_kernel() {
    if (blockIdx.y > blockIdx.x) return;   // tile fully above diagonal
    __shared__ float As[16][128];
    __shared__ float Bs[16][128];
    const int tid = threadIdx.x;
    const int tx = tid & 15, ty = tid >> 4;
    const int m0 = blockIdx.x * 128;       // query tile
    const int n0 = blockIdx.y * 128;       // key tile
    const int b  = blockIdx.z;
    const float* __restrict__ Q = g_Q + (long)b * SEQ * DIM;
    const float* __restrict__ K = g_K + (long)b * SEQ * DIM;
    float* __restrict__ Sg = g_S + (size_t)b * SEQ * SEQ;

    float acc[8][8];
#pragma unroll
    for (int i = 0; i < 8; ++i)
#pragma unroll
        for (int j = 0; j < 8; ++j) acc[i][j] = 0.f;

    for (int kk = 0; kk < DIM; kk += 16) {
        load_tile_T(Q, m0, kk, DIM, As, tid);
        load_tile_T(K, n0, kk, DIM, Bs, tid);
        __syncthreads();
        mma_16(As, Bs, ty, tx, acc);
        __syncthreads();
    }

    const float scale = 0.036084391824351615f;  // 1/sqrt(768)
#pragma unroll
    for (int i = 0; i < 8; ++i) {
        float4 v0 = make_float4(acc[i][0] * scale, acc[i][1] * scale,
                                acc[i][2] * scale, acc[i][3] * scale);
        float4 v1 = make_float4(acc[i][4] * scale, acc[i][5] * scale,
                                acc[i][6] * scale, acc[i][7] * scale);
        size_t base = (size_t)(m0 + ty * 8 + i) * SEQ + n0 + tx * 8;
        *(float4*)(Sg + base)     = v0;
        *(float4*)(Sg + base + 4) = v1;
    }
}

// ---------------- kernel 3: causal row softmax (in place) ------------------
// Row q: valid length q+1; zero-fill up to the 128-boundary so PV can read
// whole 128-wide K tiles.
__global__ __launch_bounds__(256) void softmax_kernel() {
    const int rid = blockIdx.x;             // 0 .. B*SEQ-1
    const int q = rid & (SEQ - 1);
    float* __restrict__ row = g_S + (size_t)rid * SEQ;
    const int L = q + 1;
    const int tid = threadIdx.x;
    __shared__ float red[256];

    float m = -1e30f;
    for (int k = tid; k < L; k += 256) m = fmaxf(m, row[k]);
    red[tid] = m;
    __syncthreads();
#pragma unroll
    for (int s = 128; s > 0; s >>= 1) {
        if (tid < s) red[tid] = fmaxf(red[tid], red[tid + s]);
        __syncthreads();
    }
    m = red[0];
    __syncthreads();

    float ssum = 0.f;
    for (int k = tid; k < L; k += 256) {
        float e = __expf(row[k] - m);
        row[k] = e;
        ssum += e;
    }
    red[tid] = ssum;
    __syncthreads();
#pragma unroll
    for (int s = 128; s > 0; s >>= 1) {
        if (tid < s) red[tid] += red[tid + s];
        __syncthreads();
    }
    const float inv = 1.0f / red[0];

    for (int k = tid; k < L; k += 256) row[k] *= inv;
    const int kend = (q & ~127) + 128;
    for (int k = L + tid; k < kend; k += 256) row[k] = 0.f;
}

// ---------------- kernel 4: O = P V (NN GEMM, K clipped by causality) ------
__global__ __launch_bounds__(256) void pv_kernel(float* __restrict__ out) {
    __shared__ float As[16][128];   // P transposed tile: As[k][m]
    __shared__ float Bs[16][128];   // V tile: Bs[k][n]
    const int tid = threadIdx.x;
    const int tx = tid & 15, ty = tid >> 4;
    const int m0 = blockIdx.x * 128;     // query tile
    const int n0 = blockIdx.y * 128;     // output-dim tile
    const int b  = blockIdx.z;
    const float* __restrict__ P = g_S + (size_t)b * SEQ * SEQ;
    const float* __restrict__ V = g_V + (long)b * SEQ * DIM;

    float acc[8][8];
#pragma unroll
    for (int i = 0; i < 8; ++i)
#pragma unroll
        for (int j = 0; j < 8; ++j) acc[i][j] = 0.f;

    const int kmax = m0 + 128;           // P is zero beyond the diagonal tile
    const int kr = tid >> 5;             // 0..7
    const int nc = (tid & 31) << 2;      // 0..124

    for (int kk = 0; kk < kmax; kk += 16) {
        load_tile_T(P, m0, kk, SEQ, As, tid);
#pragma unroll
        for (int i = 0; i < 2; ++i) {
            int k = kr + i * 8;
            *(float4*)&Bs[k][nc] = *(const float4*)(V + (long)(kk + k) * DIM + n0 + nc);
        }
        __syncthreads();
        mma_16(As, Bs, ty, tx, acc);
        __syncthreads();
    }

    float* __restrict__ O = out + (long)b * SEQ * DIM;
#pragma unroll
    for (int i = 0; i < 8; ++i) {
        float4 v0 = make_float4(acc[i][0], acc[i][1], acc[i][2], acc[i][3]);
        float4 v1 = make_float4(acc[i][4], acc[i][5], acc[i][6], acc[i][7]);
        long base = (long)(m0 + ty * 8 + i) * DIM + n0 + tx * 8;
        *(float4*)(O + base)     = v0;
        *(float4*)(O + base + 4) = v1;
    }
}

// ---------------- launch ----------------------------------------------------
extern "C" void kernel_launch(void* const* d_in, const int* in_sizes, int n_in,
                              void* d_out, int out_size) {
    const float* x  = (const float*)d_in[0];
    const float* Wq = (const float*)d_in[1];
    const float* Wk = (const float*)d_in[2];
    const float* Wv = (const float*)d_in[3];
    float* out = (float*)d_out;

    qkv_kernel<<<dim3(BATCH * SEQ / 128, 3 * DIM / 128), 256>>>(x, Wq, Wk, Wv);
    scores_kernel<<<dim3(SEQ / 128, SEQ / 128, BATCH), 256>>>();
    softmax_kernel<<<BATCH * SEQ, 256>>>();
    pv_kernel<<<dim3(SEQ / 128, DIM / 128, BATCH), 256>>>(out);
}

// round 2
// speedup vs baseline: 1.0342x; 1.0342x over previous
#include <cuda_runtime.h>
#include <math.h>

#define BATCH 4
#define SEQ   2048
#define DIM   768

// ---------------- device scratch (allocation-free per harness rules) -------
__device__ float g_Q[BATCH * SEQ * DIM];
__device__ float g_K[BATCH * SEQ * DIM];
__device__ float g_V[BATCH * SEQ * DIM];
__device__ float g_S[(size_t)BATCH * SEQ * SEQ];

// ---------------- packed f32x2 helpers (sm_103a) ----------------------------
__device__ __forceinline__ void fma2(unsigned long long& d, unsigned long long a,
                                     unsigned long long b) {
    asm("fma.rn.f32x2 %0, %1, %2, %0;" : "+l"(d) : "l"(a), "l"(b));
}
__device__ __forceinline__ unsigned long long pack2(float x) {
    unsigned long long r;
    asm("mov.b64 %0, {%1, %1};" : "=l"(r) : "f"(x));
    return r;
}

// ---------------- fragments & loaders ---------------------------------------
struct Frag { float4 v[2]; };

// Load a 128(rows) x 16(k) tile from row-major src, to be stored TRANSPOSED.
__device__ __forceinline__ Frag ld_g_T(const float* __restrict__ src, int row0,
                                       int kk, int ld, int tid) {
    const int lr = tid >> 2, lc = (tid & 3) << 2;
    Frag f;
    f.v[0] = *(const float4*)(src + (long)(row0 + lr) * ld + kk + lc);
    f.v[1] = *(const float4*)(src + (long)(row0 + lr + 64) * ld + kk + lc);
    return f;
}
__device__ __forceinline__ void st_s_T(float (*sm)[128], Frag f, int tid) {
    const int lr = tid >> 2, lc = (tid & 3) << 2;
#pragma unroll
    for (int i = 0; i < 2; ++i) {
        const int r = lr + i * 64;
        const float4 v = f.v[i];
        sm[lc + 0][r] = v.x; sm[lc + 1][r] = v.y;
        sm[lc + 2][r] = v.z; sm[lc + 3][r] = v.w;
    }
}
// Non-transposed loader for V (already k-major rows): Bs[k][n].
__device__ __forceinline__ Frag ld_g_NN(const float* __restrict__ V, int kk, int n0,
                                        int tid) {
    const int kr = tid >> 5, nc = (tid & 31) << 2;
    Frag f;
    f.v[0] = *(const float4*)(V + (long)(kk + kr) * DIM + n0 + nc);
    f.v[1] = *(const float4*)(V + (long)(kk + kr + 8) * DIM + n0 + nc);
    return f;
}
__device__ __forceinline__ void st_s_NN(float (*sm)[128], Frag f, int tid) {
    const int kr = tid >> 5, nc = (tid & 31) << 2;
    *(float4*)&sm[kr][nc]     = f.v[0];
    *(float4*)&sm[kr + 8][nc] = f.v[1];
}

// ---------------- 128x128x16 packed-f32x2 micro-GEMM ------------------------
// 256 threads; each owns an 8x8 microtile held as 8x4 packed f32x2 pairs.
__device__ __forceinline__ void mma16_f2(const float (*As)[128], const float (*Bs)[128],
                                         int ty, int tx, unsigned long long acc[8][4]) {
#pragma unroll
    for (int k = 0; k < 16; ++k) {
        float a[8];
        *(float4*)&a[0] = *(const float4*)&As[k][ty * 8 + 0];
        *(float4*)&a[4] = *(const float4*)&As[k][ty * 8 + 4];
        const ulonglong2 b0 = *(const ulonglong2*)&Bs[k][tx * 8 + 0];
        const ulonglong2 b1 = *(const ulonglong2*)&Bs[k][tx * 8 + 4];
        unsigned long long bb[4];
        bb[0] = b0.x; bb[1] = b0.y; bb[2] = b1.x; bb[3] = b1.y;
#pragma unroll
        for (int i = 0; i < 8; ++i) {
            const unsigned long long aa = pack2(a[i]);
#pragma unroll
            for (int j = 0; j < 4; ++j) fma2(acc[i][j], aa, bb[j]);
        }
    }
}

#define ACC_DECL unsigned long long acc[8][4];                 \
    _Pragma("unroll") for (int i = 0; i < 8; ++i)              \
    _Pragma("unroll") for (int j = 0; j < 4; ++j) acc[i][j] = 0ULL;

// ---------------- kernel 1: fused QKV projection (NT GEMM) -----------------
__global__ __launch_bounds__(256, 2) void qkv_kernel(const float* __restrict__ x,
                                                     const float* __restrict__ Wq,
                                                     const float* __restrict__ Wk,
                                                     const float* __restrict__ Wv) {
    __shared__ float As[2][16][128];
    __shared__ float Bs[2][16][128];
    const int tid = threadIdx.x;
    const int tx = tid & 15, ty = tid >> 4;
    const int m0 = blockIdx.x * 128;
    const int ng = blockIdx.y * 128;
    const int mat = ng / DIM;
    const int n0 = ng % DIM;
    const float* __restrict__ W = (mat == 0) ? Wq : ((mat == 1) ? Wk : Wv);

    ACC_DECL;

    Frag fa = ld_g_T(x, m0, 0, DIM, tid);
    Frag fb = ld_g_T(W, n0, 0, DIM, tid);
    st_s_T(As[0], fa, tid);
    st_s_T(Bs[0], fb, tid);
    __syncthreads();

    const int NT = DIM / 16;
    for (int t = 0; t < NT; ++t) {
        const int buf = t & 1;
        if (t + 1 < NT) {
            fa = ld_g_T(x, m0, (t + 1) * 16, DIM, tid);
            fb = ld_g_T(W, n0, (t + 1) * 16, DIM, tid);
        }
        mma16_f2(As[buf], Bs[buf], ty, tx, acc);
        if (t + 1 < NT) {
            st_s_T(As[buf ^ 1], fa, tid);
            st_s_T(Bs[buf ^ 1], fb, tid);
            __syncthreads();
        }
    }

    float* dst = (mat == 0) ? g_Q : ((mat == 1) ? g_K : g_V);
#pragma unroll
    for (int i = 0; i < 8; ++i) {
        const float* r = (const float*)&acc[i][0];
        long base = (long)(m0 + ty * 8 + i) * DIM + n0 + tx * 8;
        *(float4*)(dst + base)     = *(const float4*)&r[0];
        *(float4*)(dst + base + 4) = *(const float4*)&r[4];
    }
}

// ---------------- kernel 2: causal scores S = scale * Q K^T ----------------
__global__ __launch_bounds__(256, 2) void scores_kernel() {
    const int mi = gridDim.x - 1 - blockIdx.x;   // longest rows scheduled first
    if (blockIdx.y > mi) return;                 // tile fully above diagonal
    __shared__ float As[2][16][128];
    __shared__ float Bs[2][16][128];
    const int tid = threadIdx.x;
    const int tx = tid & 15, ty = tid >> 4;
    const int m0 = mi * 128;
    const int n0 = blockIdx.y * 128;
    const int b  = blockIdx.z;
    const float* __restrict__ Q = g_Q + (long)b * SEQ * DIM;
    const float* __restrict__ K = g_K + (long)b * SEQ * DIM;
    float* __restrict__ Sg = g_S + (size_t)b * SEQ * SEQ;

    ACC_DECL;

    Frag fa = ld_g_T(Q, m0, 0, DIM, tid);
    Frag fb = ld_g_T(K, n0, 0, DIM, tid);
    st_s_T(As[0], fa, tid);
    st_s_T(Bs[0], fb, tid);
    __syncthreads();

    const int NT = DIM / 16;
    for (int t = 0; t < NT; ++t) {
        const int buf = t & 1;
        if (t + 1 < NT) {
            fa = ld_g_T(Q, m0, (t + 1) * 16, DIM, tid);
            fb = ld_g_T(K, n0, (t + 1) * 16, DIM, tid);
        }
        mma16_f2(As[buf], Bs[buf], ty, tx, acc);
        if (t + 1 < NT) {
            st_s_T(As[buf ^ 1], fa, tid);
            st_s_T(Bs[buf ^ 1], fb, tid);
            __syncthreads();
        }
    }

    const float scale = 0.036084391824351615f;   // 1/sqrt(768)
#pragma unroll
    for (int i = 0; i < 8; ++i) {
        const float* r = (const float*)&acc[i][0];
        float4 v0 = make_float4(r[0] * scale, r[1] * scale, r[2] * scale, r[3] * scale);
        float4 v1 = make_float4(r[4] * scale, r[5] * scale, r[6] * scale, r[7] * scale);
        size_t base = (size_t)(m0 + ty * 8 + i) * SEQ + n0 + tx * 8;
        *(float4*)(Sg + base)     = v0;
        *(float4*)(Sg + base + 4) = v1;
    }
}

// ---------------- kernel 3: causal row softmax (in place) ------------------
__global__ __launch_bounds__(256) void softmax_kernel() {
    const int rid = blockIdx.x;
    const int q = rid & (SEQ - 1);
    float* __restrict__ row = g_S + (size_t)rid * SEQ;
    const int L = q + 1;
    const int tid = threadIdx.x;
    __shared__ float red[256];

    float m = -1e30f;
    for (int k = tid; k < L; k += 256) m = fmaxf(m, row[k]);
    red[tid] = m;
    __syncthreads();
#pragma unroll
    for (int s = 128; s > 0; s >>= 1) {
        if (tid < s) red[tid] = fmaxf(red[tid], red[tid + s]);
        __syncthreads();
    }
    m = red[0];
    __syncthreads();

    float ssum = 0.f;
    for (int k = tid; k < L; k += 256) {
        float e = __expf(row[k] - m);
        row[k] = e;
        ssum += e;
    }
    red[tid] = ssum;
    __syncthreads();
#pragma unroll
    for (int s = 128; s > 0; s >>= 1) {
        if (tid < s) red[tid] += red[tid + s];
        __syncthreads();
    }
    const float inv = 1.0f / red[0];

    for (int k = tid; k < L; k += 256) row[k] *= inv;
    const int kend = (q & ~127) + 128;
    for (int k = L + tid; k < kend; k += 256) row[k] = 0.f;
}

// ---------------- kernel 4: O = P V (NN GEMM, K clipped by causality) ------
__global__ __launch_bounds__(256, 2) void pv_kernel(float* __restrict__ out) {
    __shared__ float As[2][16][128];   // P^T tile: As[k][m]
    __shared__ float Bs[2][16][128];   // V tile:   Bs[k][n]
    const int tid = threadIdx.x;
    const int tx = tid & 15, ty = tid >> 4;
    const int mi = gridDim.x - 1 - blockIdx.x;   // longest K-ranges first
    const int m0 = mi * 128;
    const int n0 = blockIdx.y * 128;
    const int b  = blockIdx.z;
    const float* __restrict__ P = g_S + (size_t)b * SEQ * SEQ;
    const float* __restrict__ V = g_V + (long)b * SEQ * DIM;

    ACC_DECL;

    Frag fa = ld_g_T(P, m0, 0, SEQ, tid);
    Frag fb = ld_g_NN(V, 0, n0, tid);
    st_s_T(As[0], fa, tid);
    st_s_NN(Bs[0], fb, tid);
    __syncthreads();

    const int NT = (m0 + 128) / 16;    // P zero-padded to the tile boundary
    for (int t = 0; t < NT; ++t) {
        const int buf = t & 1;
        if (t + 1 < NT) {
            fa = ld_g_T(P, m0, (t + 1) * 16, SEQ, tid);
            fb = ld_g_NN(V, (t + 1) * 16, n0, tid);
        }
        mma16_f2(As[buf], Bs[buf], ty, tx, acc);
        if (t + 1 < NT) {
            st_s_T(As[buf ^ 1], fa, tid);
            st_s_NN(Bs[buf ^ 1], fb, tid);
            __syncthreads();
        }
    }

    float* __restrict__ O = out + (long)b * SEQ * DIM;
#pragma unroll
    for (int i = 0; i < 8; ++i) {
        const float* r = (const float*)&acc[i][0];
        long base = (long)(m0 + ty * 8 + i) * DIM + n0 + tx * 8;
        *(float4*)(O + base)     = *(const float4*)&r[0];
        *(float4*)(O + base + 4) = *(const float4*)&r[4];
    }
}

// ---------------- launch ----------------------------------------------------
extern "C" void kernel_launch(void* const* d_in, const int* in_sizes, int n_in,
                              void* d_out, int out_size) {
    const float* x  = (const float*)d_in[0];
    const float* Wq = (const float*)d_in[1];
    const float* Wk = (const float*)d_in[2];
    const float* Wv = (const float*)d_in[3];
    float* out = (float*)d_out;

    qkv_kernel<<<dim3(BATCH * SEQ / 128, 3 * DIM / 128), 256>>>(x, Wq, Wk, Wv);
    scores_kernel<<<dim3(SEQ / 128, SEQ / 128, BATCH), 256>>>();
    softmax_kernel<<<BATCH * SEQ, 256>>>();
    pv_kernel<<<dim3(SEQ / 128, DIM / 128, BATCH), 256>>>(out);
}

// round 4
// speedup vs baseline: 2.2972x; 2.2213x over previous
#include <cuda_runtime.h>
#include <cuda_bf16.h>
#include <stdint.h>

#define BATCH 4
#define SEQ   2048
#define DIM   768
#define MROWS 8192            // B*S
#define NQKV  2304            // 3*DIM

// ---------------- device scratch: split-bf16 planes -------------------------
__device__ __align__(128) __nv_bfloat16 g_xh[(long)MROWS * DIM];
__device__ __align__(128) __nv_bfloat16 g_xl[(long)MROWS * DIM];
__device__ __align__(128) __nv_bfloat16 g_wh[(long)NQKV * DIM];
__device__ __align__(128) __nv_bfloat16 g_wl[(long)NQKV * DIM];
__device__ __align__(128) __nv_bfloat16 g_qh[(long)MROWS * DIM];
__device__ __align__(128) __nv_bfloat16 g_ql[(long)MROWS * DIM];
__device__ __align__(128) __nv_bfloat16 g_kh[(long)MROWS * DIM];
__device__ __align__(128) __nv_bfloat16 g_kl[(long)MROWS * DIM];
__device__ __align__(128) __nv_bfloat16 g_vh[(long)MROWS * DIM];   // [b*S+s][d]
__device__ __align__(128) __nv_bfloat16 g_vl[(long)MROWS * DIM];
__device__ __align__(128) __nv_bfloat16 g_ph[(size_t)BATCH * SEQ * SEQ];
__device__ __align__(128) __nv_bfloat16 g_pl[(size_t)BATCH * SEQ * SEQ];
__device__ float g_S[(size_t)BATCH * SEQ * SEQ];

// ---------------- PTX helpers (all portable, no arch-'a' features) ----------
__device__ __forceinline__ uint32_t smem_u32(const void* p) {
    uint32_t a;
    asm("{ .reg .u64 t; cvta.to.shared.u64 t, %1; cvt.u32.u64 %0, t; }"
        : "=r"(a) : "l"(p));
    return a;
}
__device__ __forceinline__ void ldsm4(uint32_t r[4], uint32_t addr) {
    asm volatile("ldmatrix.sync.aligned.m8n8.x4.shared.b16 {%0,%1,%2,%3}, [%4];"
                 : "=r"(r[0]), "=r"(r[1]), "=r"(r[2]), "=r"(r[3]) : "r"(addr));
}
__device__ __forceinline__ void ldsm4t(uint32_t r[4], uint32_t addr) {
    asm volatile("ldmatrix.sync.aligned.m8n8.x4.trans.shared.b16 {%0,%1,%2,%3}, [%4];"
                 : "=r"(r[0]), "=r"(r[1]), "=r"(r[2]), "=r"(r[3]) : "r"(addr));
}
__device__ __forceinline__ void mma16816(float d[4], const uint32_t a[4],
                                         const uint32_t b[2]) {
    asm volatile(
        "mma.sync.aligned.m16n8k16.row.col.f32.bf16.bf16.f32 "
        "{%0,%1,%2,%3}, {%4,%5,%6,%7}, {%8,%9}, {%0,%1,%2,%3};"
        : "+f"(d[0]), "+f"(d[1]), "+f"(d[2]), "+f"(d[3])
        : "r"(a[0]), "r"(a[1]), "r"(a[2]), "r"(a[3]), "r"(b[0]), "r"(b[1]));
}
__device__ __forceinline__ void split_bf16(float v, __nv_bfloat16& h, __nv_bfloat16& l) {
    h = __float2bfloat16(v);
    l = __float2bfloat16(v - __bfloat162float(h));
}

// smem geometry: padded rows of 24 bf16 (48B) -> conflict-free ldmatrix
#define ROWB   48
#define PLANE  (128 * ROWB)          // 6144 B, one operand plane (128 x k16)
#define STAGE  (2 * PLANE)           // 12288 B, both planes

// ---------------- stage compute: NT (B as [n][k]) ---------------------------
// sa/sb: byte base of stage (plane0); acc[mi][nj][4]
__device__ __forceinline__ void stage_nt(uint32_t sa, uint32_t sb, int lane,
                                         int wm, int wn, float acc[4][4][4]) {
    const int lr = lane & 15;
    const uint32_t lc16 = (lane >> 4) << 4;
    uint32_t bh[4][2], bl[4][2];
#pragma unroll
    for (int j = 0; j < 2; ++j) {
        uint32_t t4[4];
        const uint32_t roff = (uint32_t)(wn * 32 + j * 16 + lr) * ROWB + lc16;
        ldsm4(t4, sb + roff);
        bh[j*2][0] = t4[0]; bh[j*2+1][0] = t4[1];
        bh[j*2][1] = t4[2]; bh[j*2+1][1] = t4[3];
        ldsm4(t4, sb + PLANE + roff);
        bl[j*2][0] = t4[0]; bl[j*2+1][0] = t4[1];
        bl[j*2][1] = t4[2]; bl[j*2+1][1] = t4[3];
    }
#pragma unroll
    for (int mi = 0; mi < 4; ++mi) {
        uint32_t ah[4], al[4];
        const uint32_t roff = (uint32_t)(wm * 64 + mi * 16 + lr) * ROWB + lc16;
        ldsm4(ah, sa + roff);
        ldsm4(al, sa + PLANE + roff);
#pragma unroll
        for (int nj = 0; nj < 4; ++nj) {
            mma16816(acc[mi][nj], ah, bh[nj]);
            mma16816(acc[mi][nj], ah, bl[nj]);
            mma16816(acc[mi][nj], al, bh[nj]);
        }
    }
}

// ---------------- stage compute: PV (B = V stored [s][d], trans ldmatrix) ---
#define VROWB  272                       // 136 bf16 padded row
#define VPLANE (16 * VROWB)              // 4352 B
#define VSTAGE (2 * VPLANE)

__device__ __forceinline__ void stage_pv(uint32_t sa, uint32_t sv, int lane,
                                         int wm, int wn, float acc[4][4][4]) {
    const int lr = lane & 15;
    const uint32_t lc16 = (lane >> 4) << 4;
    uint32_t bh[4][2], bl[4][2];
#pragma unroll
    for (int j = 0; j < 2; ++j) {
        uint32_t t4[4];
        const uint32_t off = (uint32_t)lr * VROWB + (uint32_t)(wn * 32 + j * 16) * 2 + lc16;
        ldsm4t(t4, sv + off);
        bh[j*2][0] = t4[0]; bh[j*2][1] = t4[1];
        bh[j*2+1][0] = t4[2]; bh[j*2+1][1] = t4[3];
        ldsm4t(t4, sv + VPLANE + off);
        bl[j*2][0] = t4[0]; bl[j*2][1] = t4[1];
        bl[j*2+1][0] = t4[2]; bl[j*2+1][1] = t4[3];
    }
#pragma unroll
    for (int mi = 0; mi < 4; ++mi) {
        uint32_t ah[4], al[4];
        const uint32_t roff = (uint32_t)(wm * 64 + mi * 16 + lr) * ROWB + lc16;
        ldsm4(ah, sa + roff);
        ldsm4(al, sa + PLANE + roff);
#pragma unroll
        for (int nj = 0; nj < 4; ++nj) {
            mma16816(acc[mi][nj], ah, bh[nj]);
            mma16816(acc[mi][nj], ah, bl[nj]);
            mma16816(acc[mi][nj], al, bh[nj]);
        }
    }
}

#define ACC_INIT float acc[4][4][4];                                    \
    _Pragma("unroll") for (int _i = 0; _i < 4; ++_i)                    \
    _Pragma("unroll") for (int _j = 0; _j < 4; ++_j)                    \
    _Pragma("unroll") for (int _k = 0; _k < 4; ++_k) acc[_i][_j][_k] = 0.f;

// ---------------- NT mainloop (qkv / scores) --------------------------------
// A,B: split planes, row-major [row][K], row strides lda/ldb (elements).
#define NT_MAINLOOP(Ah, Al, Bh, Bl, lda, ldb, NC)                              \
    __shared__ __align__(128) __nv_bfloat16 sA[2][2][128][24];                 \
    __shared__ __align__(128) __nv_bfloat16 sB[2][2][128][24];                 \
    const int tid = threadIdx.x;                                               \
    const int lane = tid & 31, wid = tid >> 5;                                 \
    const int wm = wid >> 2, wn = wid & 3;                                     \
    const int lrow = tid >> 1, lhalf = tid & 1;                                \
    const uint32_t sau = smem_u32(&sA[0][0][0][0]);                            \
    const uint32_t sbu = smem_u32(&sB[0][0][0][0]);                            \
    ACC_INIT;                                                                  \
    {                                                                          \
        uint4 a0 = *(const uint4*)(Ah + (long)lrow * (lda) + lhalf * 8);       \
        uint4 a1 = *(const uint4*)(Al + (long)lrow * (lda) + lhalf * 8);       \
        uint4 b0 = *(const uint4*)(Bh + (long)lrow * (ldb) + lhalf * 8);       \
        uint4 b1 = *(const uint4*)(Bl + (long)lrow * (ldb) + lhalf * 8);       \
        *(uint4*)&sA[0][0][lrow][lhalf * 8] = a0;                              \
        *(uint4*)&sA[0][1][lrow][lhalf * 8] = a1;                              \
        *(uint4*)&sB[0][0][lrow][lhalf * 8] = b0;                              \
        *(uint4*)&sB[0][1][lrow][lhalf * 8] = b1;                              \
    }                                                                          \
    __syncthreads();                                                           \
    for (int c = 0; c < (NC); ++c) {                                           \
        const int st = c & 1;                                                  \
        uint4 a0, a1, b0, b1;                                                  \
        if (c + 1 < (NC)) {                                                    \
            const int k0 = (c + 1) * 16 + lhalf * 8;                           \
            a0 = *(const uint4*)(Ah + (long)lrow * (lda) + k0);                \
            a1 = *(const uint4*)(Al + (long)lrow * (lda) + k0);                \
            b0 = *(const uint4*)(Bh + (long)lrow * (ldb) + k0);                \
            b1 = *(const uint4*)(Bl + (long)lrow * (ldb) + k0);                \
        }                                                                      \
        stage_nt(sau + st * STAGE, sbu + st * STAGE, lane, wm, wn, acc);       \
        if (c + 1 < (NC)) {                                                    \
            const int ns = st ^ 1;                                             \
            *(uint4*)&sA[ns][0][lrow][lhalf * 8] = a0;                         \
            *(uint4*)&sA[ns][1][lrow][lhalf * 8] = a1;                         \
            *(uint4*)&sB[ns][0][lrow][lhalf * 8] = b0;                         \
            *(uint4*)&sB[ns][1][lrow][lhalf * 8] = b1;                         \
            __syncthreads();                                                   \
        }                                                                      \
    }

// ---------------- kernel 0: fp32 -> split planes -----------------------------
__global__ __launch_bounds__(256) void cvt_kernel(const float* __restrict__ src,
                                                  int which, long row0) {
    const long i = ((long)blockIdx.x * 256 + threadIdx.x) * 4;
    __nv_bfloat16* dh = (which == 0) ? g_xh : g_wh;
    __nv_bfloat16* dl = (which == 0) ? g_xl : g_wl;
    dh += row0 * DIM;
    dl += row0 * DIM;
    const float4 v = *(const float4*)(src + i);
    float a[4] = { v.x, v.y, v.z, v.w };
    __nv_bfloat16 h[4], l[4];
#pragma unroll
    for (int j = 0; j < 4; ++j) split_bf16(a[j], h[j], l[j]);
    *(uint2*)(dh + i) = *(uint2*)h;
    *(uint2*)(dl + i) = *(uint2*)l;
}

// ---------------- kernel 1: QKV projection (NT) ------------------------------
__global__ __launch_bounds__(256, 2) void gemm_qkv() {
    const int m0 = blockIdx.x * 128;
    const int n0 = blockIdx.y * 128;
    NT_MAINLOOP(g_xh + (long)m0 * DIM, g_xl + (long)m0 * DIM,
                g_wh + (long)n0 * DIM, g_wl + (long)n0 * DIM,
                DIM, DIM, DIM / 16);

    const int mat = n0 / DIM;
    const int nl0 = n0 % DIM;
    __nv_bfloat16* dh = (mat == 0) ? g_qh : ((mat == 1) ? g_kh : g_vh);
    __nv_bfloat16* dl = (mat == 0) ? g_ql : ((mat == 1) ? g_kl : g_vl);
    const int r = lane >> 2, cc = (lane & 3) * 2;
#pragma unroll
    for (int mi = 0; mi < 4; ++mi)
#pragma unroll
        for (int nj = 0; nj < 4; ++nj)
#pragma unroll
            for (int h2 = 0; h2 < 2; ++h2) {
                const float v0 = acc[mi][nj][h2 * 2 + 0];
                const float v1 = acc[mi][nj][h2 * 2 + 1];
                const int m = m0 + wm * 64 + mi * 16 + r + h2 * 8;
                const int n = nl0 + wn * 32 + nj * 8 + cc;
                __nv_bfloat162 hv, lv;
                split_bf16(v0, hv.x, lv.x);
                split_bf16(v1, hv.y, lv.y);
                *(__nv_bfloat162*)(dh + (long)m * DIM + n) = hv;
                *(__nv_bfloat162*)(dl + (long)m * DIM + n) = lv;
            }
}

// ---------------- kernel 2: causal scores (NT) -------------------------------
__global__ __launch_bounds__(256, 2) void gemm_scores() {
    const int mi_t = gridDim.x - 1 - blockIdx.x;    // longest first
    if ((int)blockIdx.y > mi_t) return;             // fully above diagonal
    const int m0 = mi_t * 128, n0 = blockIdx.y * 128, b = blockIdx.z;
    NT_MAINLOOP(g_qh + ((long)b * SEQ + m0) * DIM, g_ql + ((long)b * SEQ + m0) * DIM,
                g_kh + ((long)b * SEQ + n0) * DIM, g_kl + ((long)b * SEQ + n0) * DIM,
                DIM, DIM, DIM / 16);

    const float scale = 0.036084391824351615f;      // 1/sqrt(768)
    float* Sg = g_S + (size_t)b * SEQ * SEQ;
    const int r = lane >> 2, cc = (lane & 3) * 2;
#pragma unroll
    for (int mi = 0; mi < 4; ++mi)
#pragma unroll
        for (int nj = 0; nj < 4; ++nj)
#pragma unroll
            for (int h2 = 0; h2 < 2; ++h2) {
                const int m = m0 + wm * 64 + mi * 16 + r + h2 * 8;
                const int n = n0 + wn * 32 + nj * 8 + cc;
                float2 v = make_float2(acc[mi][nj][h2 * 2 + 0] * scale,
                                       acc[mi][nj][h2 * 2 + 1] * scale);
                *(float2*)(Sg + (size_t)m * SEQ + n) = v;
            }
}

// ---------------- kernel 3: softmax + split-bf16 P ---------------------------
__global__ __launch_bounds__(256) void softmax_kernel() {
    const int rid = blockIdx.x;
    const int q = rid & (SEQ - 1);
    float* __restrict__ row = g_S + (size_t)rid * SEQ;
    __nv_bfloat16* __restrict__ ph = g_ph + (size_t)rid * SEQ;
    __nv_bfloat16* __restrict__ pl = g_pl + (size_t)rid * SEQ;
    const int L = q + 1;
    const int tid = threadIdx.x;
    __shared__ float red[256];

    float m = -1e30f;
    for (int k = tid; k < L; k += 256) m = fmaxf(m, row[k]);
    red[tid] = m;
    __syncthreads();
#pragma unroll
    for (int s = 128; s > 0; s >>= 1) {
        if (tid < s) red[tid] = fmaxf(red[tid], red[tid + s]);
        __syncthreads();
    }
    m = red[0];
    __syncthreads();

    float ssum = 0.f;
    for (int k = tid; k < L; k += 256) {
        float e = __expf(row[k] - m);
        row[k] = e;
        ssum += e;
    }
    red[tid] = ssum;
    __syncthreads();
#pragma unroll
    for (int s = 128; s > 0; s >>= 1) {
        if (tid < s) red[tid] += red[tid + s];
        __syncthreads();
    }
    const float inv = 1.0f / red[0];

    for (int k = tid; k < L; k += 256) {
        __nv_bfloat16 h, l;
        split_bf16(row[k] * inv, h, l);
        ph[k] = h;
        pl[k] = l;
    }
    const int kend = (q & ~127) + 128;
    const __nv_bfloat16 z = __float2bfloat16(0.f);
    for (int k = L + tid; k < kend; k += 256) { ph[k] = z; pl[k] = z; }
}

// ---------------- kernel 4: O = P V ------------------------------------------
__global__ __launch_bounds__(256, 2) void gemm_pv(float* __restrict__ out) {
    const int mi_t = gridDim.x - 1 - blockIdx.x;    // longest K first
    const int m0 = mi_t * 128, n0 = blockIdx.y * 128, b = blockIdx.z;
    const __nv_bfloat16* Ph = g_ph + ((size_t)b * SEQ + m0) * SEQ;
    const __nv_bfloat16* Pl = g_pl + ((size_t)b * SEQ + m0) * SEQ;
    const __nv_bfloat16* Vh = g_vh + (long)b * SEQ * DIM;
    const __nv_bfloat16* Vl = g_vl + (long)b * SEQ * DIM;

    __shared__ __align__(128) __nv_bfloat16 sP[2][2][128][24];
    __shared__ __align__(128) __nv_bfloat16 sV[2][2][16][136];
    const int tid = threadIdx.x;
    const int lane = tid & 31, wid = tid >> 5;
    const int wm = wid >> 2, wn = wid & 3;
    const int lrow = tid >> 1, lhalf = tid & 1;
    const int vs = tid >> 4, vc = (tid & 15) * 8;   // V loader: row s, col (bf16)
    const uint32_t spu = smem_u32(&sP[0][0][0][0]);
    const uint32_t svu = smem_u32(&sV[0][0][0][0]);
    ACC_INIT;
    const int NC = (m0 + 128) / 16;

    {
        uint4 p0 = *(const uint4*)(Ph + (long)lrow * SEQ + lhalf * 8);
        uint4 p1 = *(const uint4*)(Pl + (long)lrow * SEQ + lhalf * 8);
        uint4 v0 = *(const uint4*)(Vh + (long)vs * DIM + n0 + vc);
        uint4 v1 = *(const uint4*)(Vl + (long)vs * DIM + n0 + vc);
        *(uint4*)&sP[0][0][lrow][lhalf * 8] = p0;
        *(uint4*)&sP[0][1][lrow][lhalf * 8] = p1;
        *(uint4*)&sV[0][0][vs][vc] = v0;
        *(uint4*)&sV[0][1][vs][vc] = v1;
    }
    __syncthreads();
    for (int c = 0; c < NC; ++c) {
        const int st = c & 1;
        uint4 p0, p1, v0, v1;
        if (c + 1 < NC) {
            const int k0 = (c + 1) * 16;
            p0 = *(const uint4*)(Ph + (long)lrow * SEQ + k0 + lhalf * 8);
            p1 = *(const uint4*)(Pl + (long)lrow * SEQ + k0 + lhalf * 8);
            v0 = *(const uint4*)(Vh + (long)(k0 + vs) * DIM + n0 + vc);
            v1 = *(const uint4*)(Vl + (long)(k0 + vs) * DIM + n0 + vc);
        }
        stage_pv(spu + st * STAGE, svu + st * VSTAGE, lane, wm, wn, acc);
        if (c + 1 < NC) {
            const int ns = st ^ 1;
            *(uint4*)&sP[ns][0][lrow][lhalf * 8] = p0;
            *(uint4*)&sP[ns][1][lrow][lhalf * 8] = p1;
            *(uint4*)&sV[ns][0][vs][vc] = v0;
            *(uint4*)&sV[ns][1][vs][vc] = v1;
            __syncthreads();
        }
    }

    float* Og = out + (long)b * SEQ * DIM;
    const int r = lane >> 2, cc = (lane & 3) * 2;
#pragma unroll
    for (int mi = 0; mi < 4; ++mi)
#pragma unroll
        for (int nj = 0; nj < 4; ++nj)
#pragma unroll
            for (int h2 = 0; h2 < 2; ++h2) {
                const int m = m0 + wm * 64 + mi * 16 + r + h2 * 8;
                const int n = n0 + wn * 32 + nj * 8 + cc;
                float2 v = make_float2(acc[mi][nj][h2 * 2 + 0],
                                       acc[mi][nj][h2 * 2 + 1]);
                *(float2*)(Og + (long)m * DIM + n) = v;
            }
}

// ---------------- launch ------------------------------------------------------
extern "C" void kernel_launch(void* const* d_in, const int* in_sizes, int n_in,
                              void* d_out, int out_size) {
    const float* x  = (const float*)d_in[0];
    const float* Wq = (const float*)d_in[1];
    const float* Wk = (const float*)d_in[2];
    const float* Wv = (const float*)d_in[3];
    float* out = (float*)d_out;

    cvt_kernel<<<(long)MROWS * DIM / 4 / 256, 256>>>(x,  0, 0);
    cvt_kernel<<<(long)DIM * DIM / 4 / 256, 256>>>(Wq, 1, 0);
    cvt_kernel<<<(long)DIM * DIM / 4 / 256, 256>>>(Wk, 1, DIM);
    cvt_kernel<<<(long)DIM * DIM / 4 / 256, 256>>>(Wv, 1, 2 * DIM);

    gemm_qkv<<<dim3(MROWS / 128, NQKV / 128), 256>>>();
    gemm_scores<<<dim3(SEQ / 128, SEQ / 128, BATCH), 256>>>();
    softmax_kernel<<<BATCH * SEQ, 256>>>();
    gemm_pv<<<dim3(SEQ / 128, DIM / 128, BATCH), 256>>>(out);
}